// round 1
// baseline (speedup 1.0000x reference)
#include <cuda_runtime.h>
#include <cuda_bf16.h>
#include <math.h>

#define NUM_NODES 9
#define HIDDEN    512
#define BATCH     8192
#define M_ROWS    (BATCH * NUM_NODES)   // 73728
#define EPS       1e-8f

// Single scratch buffer (x_proj -> normalized h -> mobius result, in place).
__device__ float g_scratch[(size_t)M_ROWS * HIDDEN];

// ---------------------------------------------------------------------------
// SGEMM: C[m][n] = sum_k A[m][k] * W[n][k] + bias[n]
// A: [M,512] row-major, W: [512,512] row-major (K contiguous), C: [M,512]
// Tiles: BM=128, BN=128, BK=16, 256 threads, 8x8 per thread via fma.rn.f32x2
// ---------------------------------------------------------------------------
__global__ __launch_bounds__(256, 2)
void sgemm512_bias(const float* __restrict__ A,
                   const float* __restrict__ W,
                   const float* __restrict__ bias,
                   float* __restrict__ C)
{
    __shared__ __align__(16) float As[16][256];  // duplicated: As[k][2m]=As[k][2m+1]=a
    __shared__ __align__(16) float Bs[16][128];

    const int tid  = threadIdx.x;
    const int tx   = tid & 15;        // 0..15 -> N
    const int ty   = tid >> 4;        // 0..15 -> M
    const int bm   = blockIdx.y * 128;
    const int bn   = blockIdx.x * 128;
    const int lrow = tid >> 2;        // 0..63
    const int lk4  = (tid & 3) << 2;  // 0,4,8,12

    unsigned long long acc[8][4];
#pragma unroll
    for (int i = 0; i < 8; i++)
#pragma unroll
        for (int j = 0; j < 4; j++)
            acc[i][j] = 0ULL;         // packed (0.f, 0.f)

    for (int k0 = 0; k0 < 512; k0 += 16) {
        // Load A tile (duplicated for f32x2 splats)
#pragma unroll
        for (int p = 0; p < 2; ++p) {
            int row = lrow + p * 64;
            float4 v = *(const float4*)&A[(size_t)(bm + row) * 512 + k0 + lk4];
            *(float2*)&As[lk4 + 0][2 * row] = make_float2(v.x, v.x);
            *(float2*)&As[lk4 + 1][2 * row] = make_float2(v.y, v.y);
            *(float2*)&As[lk4 + 2][2 * row] = make_float2(v.z, v.z);
            *(float2*)&As[lk4 + 3][2 * row] = make_float2(v.w, v.w);
        }
        // Load B tile (transposed to k-major)
#pragma unroll
        for (int p = 0; p < 2; ++p) {
            int row = lrow + p * 64;
            float4 v = *(const float4*)&W[(size_t)(bn + row) * 512 + k0 + lk4];
            Bs[lk4 + 0][row] = v.x;
            Bs[lk4 + 1][row] = v.y;
            Bs[lk4 + 2][row] = v.z;
            Bs[lk4 + 3][row] = v.w;
        }
        __syncthreads();

#pragma unroll
        for (int k = 0; k < 16; ++k) {
            unsigned long long asp[8];
#pragma unroll
            for (int i = 0; i < 8; i++)
                asp[i] = *(const unsigned long long*)&As[k][2 * (ty * 8 + i)];
            ulonglong2 b0 = *(const ulonglong2*)&Bs[k][tx * 8];
            ulonglong2 b1 = *(const ulonglong2*)&Bs[k][tx * 8 + 4];
            unsigned long long bb[4] = {b0.x, b0.y, b1.x, b1.y};
#pragma unroll
            for (int i = 0; i < 8; i++)
#pragma unroll
                for (int j = 0; j < 4; j++)
                    asm("fma.rn.f32x2 %0, %1, %2, %0;"
                        : "+l"(acc[i][j]) : "l"(asp[i]), "l"(bb[j]));
        }
        __syncthreads();
    }

    // Epilogue: bias + store (packed pairs map to consecutive n)
#pragma unroll
    for (int i = 0; i < 8; i++) {
        const size_t mrow = (size_t)(bm + ty * 8 + i) * 512;
#pragma unroll
        for (int j = 0; j < 4; j++) {
            int n = bn + tx * 8 + 2 * j;
            unsigned long long bp = *(const unsigned long long*)&bias[n];
            unsigned long long o;
            asm("add.rn.f32x2 %0, %1, %2;" : "=l"(o) : "l"(acc[i][j]), "l"(bp));
            *(unsigned long long*)&C[mrow + n] = o;
        }
    }
}

// ---------------------------------------------------------------------------
// Mobius aggregation: one block per batch element, 9 warps (one per node).
// Reads x_proj rows, tanh-normalizes, runs the per-node mobius chains,
// writes the result IN PLACE (safe: all reads go through smem, loaded first).
// ---------------------------------------------------------------------------
__device__ __forceinline__ float warpSum(float v) {
    v += __shfl_xor_sync(0xffffffffu, v, 16);
    v += __shfl_xor_sync(0xffffffffu, v, 8);
    v += __shfl_xor_sync(0xffffffffu, v, 4);
    v += __shfl_xor_sync(0xffffffffu, v, 2);
    v += __shfl_xor_sync(0xffffffffu, v, 1);
    return v;
}

__device__ const int d_ncnt[9]   = {3, 3, 2, 3, 3, 2, 3, 3, 8};
__device__ const int d_nbr[9][8] = {
    {4, 7, 8, 0, 0, 0, 0, 0},
    {0, 6, 8, 0, 0, 0, 0, 0},
    {5, 8, 0, 0, 0, 0, 0, 0},
    {1, 4, 8, 0, 0, 0, 0, 0},
    {6, 3, 8, 0, 0, 0, 0, 0},
    {2, 8, 0, 0, 0, 0, 0, 0},
    {7, 1, 8, 0, 0, 0, 0, 0},
    {3, 0, 8, 0, 0, 0, 0, 0},
    {0, 1, 2, 3, 4, 5, 6, 7}
};

__global__ __launch_bounds__(288)
void mobius_kernel(float* __restrict__ buf,          // in: x_proj, out: r (in place)
                   const float* __restrict__ mw,     // [9,9,512]
                   const float* __restrict__ curv)
{
    __shared__ __align__(16) float sh[NUM_NODES * HIDDEN];
    __shared__ float sh_xx[NUM_NODES];

    const int b   = blockIdx.x;
    const int tid = threadIdx.x;
    const float c = fabsf(curv[0]);
    float* base = buf + (size_t)b * NUM_NODES * HIDDEN;

    // cooperative load of all 9 node rows
    for (int idx = tid; idx < NUM_NODES * HIDDEN / 4; idx += 288)
        ((float4*)sh)[idx] = ((const float4*)base)[idx];
    __syncthreads();

    const int w    = tid >> 5;     // node / chain id, 0..8
    const int lane = tid & 31;

    // tanh-normalize node w
    float r[16];
    float n2 = 0.f;
#pragma unroll
    for (int u = 0; u < 16; u++) {
        r[u] = sh[w * HIDDEN + u * 32 + lane];
        n2 += r[u] * r[u];
    }
    n2 = warpSum(n2);
    float norm  = sqrtf(n2);
    float scale = tanhf(norm) / (norm + EPS);
#pragma unroll
    for (int u = 0; u < 16; u++) {
        r[u] *= scale;
        sh[w * HIDDEN + u * 32 + lane] = r[u];
    }
    if (lane == 0) sh_xx[w] = scale * scale * n2;
    __syncthreads();

    // mobius chain for node w
    const int cnt = d_ncnt[w];
    for (int q = 0; q < cnt; q++) {
        const int j = d_nbr[w][q];
        const float* mwp = mw + ((size_t)w * NUM_NODES + j) * HIDDEN;

        float hj[16], mv[16];
        float xy = 0.f, yy = 0.f;
#pragma unroll
        for (int u = 0; u < 16; u++) {
            hj[u] = sh[j * HIDDEN + u * 32 + lane];
            mv[u] = mwp[u * 32 + lane];
            xy += hj[u] * mv[u];
            yy += mv[u] * mv[u];
        }
        xy = warpSum(xy);
        yy = warpSum(yy);
        const float xxj = sh_xx[j];

        // t = mobius_add(h_j, mw_ij, c)
        float ca   = 1.f + 2.f * c * xy + c * yy;
        float cb   = 1.f - c * xxj;
        float inv  = 1.f / (1.f + 2.f * c * xy + c * c * xxj * yy + EPS);

        float t[16];
        float rt = 0.f, tt = 0.f, rr = 0.f;
#pragma unroll
        for (int u = 0; u < 16; u++) {
            t[u] = (ca * hj[u] + cb * mv[u]) * inv;
            rt += r[u] * t[u];
            tt += t[u] * t[u];
            rr += r[u] * r[u];
        }
        rt = warpSum(rt);
        tt = warpSum(tt);
        rr = warpSum(rr);

        // r = mobius_add(r, t, c)
        float ca2  = 1.f + 2.f * c * rt + c * tt;
        float cb2  = 1.f - c * rr;
        float inv2 = 1.f / (1.f + 2.f * c * rt + c * c * rr * tt + EPS);
#pragma unroll
        for (int u = 0; u < 16; u++)
            r[u] = (ca2 * r[u] + cb2 * t[u]) * inv2;
    }

    // write back (in place)
    float* dst = base + (size_t)w * HIDDEN;
#pragma unroll
    for (int u = 0; u < 16; u++)
        dst[u * 32 + lane] = r[u];
}

// ---------------------------------------------------------------------------
// kernel_launch
// Inputs (metadata order):
//   0 node_features [8192,9,512] f32
//   1 curvature     scalar f32
//   2 to_w          [512,512] f32
//   3 to_b          [512] f32
//   4 from_w        [512,512] f32
//   5 from_b        [512] f32
//   6 mobius_weights[9,9,512] f32
// Output: [8192,9,512] f32
// ---------------------------------------------------------------------------
extern "C" void kernel_launch(void* const* d_in, const int* in_sizes, int n_in,
                              void* d_out, int out_size)
{
    const float* nf     = (const float*)d_in[0];
    const float* curv   = (const float*)d_in[1];
    const float* to_w   = (const float*)d_in[2];
    const float* to_b   = (const float*)d_in[3];
    const float* from_w = (const float*)d_in[4];
    const float* from_b = (const float*)d_in[5];
    const float* mw     = (const float*)d_in[6];
    float* out = (float*)d_out;

    float* scratch;
    cudaGetSymbolAddress((void**)&scratch, g_scratch);

    dim3 gemm_grid(512 / 128, M_ROWS / 128);  // (4, 576)
    dim3 gemm_block(256);

    // 1) x_proj = nf @ to_w.T + to_b  -> scratch
    sgemm512_bias<<<gemm_grid, gemm_block>>>(nf, to_w, to_b, scratch);

    // 2) tanh-normalize + mobius chains, in place on scratch
    mobius_kernel<<<BATCH, 288>>>(scratch, mw, curv);

    // 3) out = r @ from_w.T + from_b
    sgemm512_bias<<<gemm_grid, gemm_block>>>(scratch, from_w, from_b, out);
}

// round 3
// speedup vs baseline: 2.3856x; 2.3856x over previous
#include <cuda_runtime.h>
#include <cuda_bf16.h>
#include <math.h>
#include <cstdint>

#define NUM_NODES 9
#define HIDDEN    512
#define BATCH     8192
#define M_ROWS    (BATCH * NUM_NODES)   // 73728
#define EPS       1e-8f

// Single f32 scratch (x_proj -> h -> mobius result, in place).
__device__ float g_scratch[(size_t)M_ROWS * HIDDEN];

// ---------------------------------------------------------------------------
// TF32 mma.sync GEMM:  C[m][n] = sum_k A[m][k] * W[n][k] + bias[n]
// CTA tile 128x128, BK=32, 256 threads, 8 warps (2 M x 4 N), warp tile 64x32.
// Smem [row][36] padding: fragment LDS and staging STS conflict-free.
// ---------------------------------------------------------------------------
#define BM 128
#define BN 128
#define BK 32
#define LDS_PITCH 36                     // 32 + 4 pad (floats)
#define KCHUNKS (HIDDEN / BK)            // 16
#define BUF_FLOATS (BM * LDS_PITCH)      // 4608 per operand
#define DYN_SMEM_BYTES (4 * BUF_FLOATS * 4)  // A0,B0,A1,B1 = 73728 B

__device__ __forceinline__ uint32_t cvt_tf32(float f) {
    uint32_t u;
    asm("cvt.rna.tf32.f32 %0, %1;" : "=r"(u) : "f"(f));
    return u;
}

__device__ __forceinline__ void mma_tf32(float* d, const uint32_t* a, const uint32_t* b) {
    asm volatile(
        "mma.sync.aligned.m16n8k8.row.col.f32.tf32.tf32.f32 "
        "{%0,%1,%2,%3}, {%4,%5,%6,%7}, {%8,%9}, {%0,%1,%2,%3};"
        : "+f"(d[0]), "+f"(d[1]), "+f"(d[2]), "+f"(d[3])
        : "r"(a[0]), "r"(a[1]), "r"(a[2]), "r"(a[3]), "r"(b[0]), "r"(b[1]));
}

__global__ __launch_bounds__(256, 2)
void gemm_tf32(const float* __restrict__ A,
               const float* __restrict__ W,
               const float* __restrict__ bias,
               float* __restrict__ C)
{
    extern __shared__ __align__(16) float smem[];
    float* sA[2] = { smem,                  smem + 2 * BUF_FLOATS };
    float* sB[2] = { smem + BUF_FLOATS,     smem + 3 * BUF_FLOATS };

    const int tid  = threadIdx.x;
    const int bm   = blockIdx.y * BM;
    const int bn   = blockIdx.x * BN;
    const int lane = tid & 31;
    const int wid  = tid >> 5;
    const int m0w  = (wid & 1) * 64;      // warp M origin within tile
    const int n0w  = (wid >> 1) * 32;     // warp N origin within tile
    const int g    = lane >> 2;           // group id 0..7
    const int t    = lane & 3;            // thread-in-group 0..3

    const int r = tid >> 3;               // staging row 0..31 (x4 iters -> 0..127)
    const int q = tid & 7;                // staging float4-col 0..7

    const float4* A4 = (const float4*)A;
    const float4* W4 = (const float4*)W;

    float acc[4][4][4];
#pragma unroll
    for (int mi = 0; mi < 4; mi++)
#pragma unroll
        for (int ni = 0; ni < 4; ni++)
#pragma unroll
            for (int e = 0; e < 4; e++) acc[mi][ni][e] = 0.f;

    float4 ra[4], rb[4];

    // ---- prologue: chunk 0 ----
#pragma unroll
    for (int i = 0; i < 4; i++) {
        int rr = r + i * 32;
        ra[i] = A4[(size_t)(bm + rr) * 128 + q];
        rb[i] = W4[(size_t)(bn + rr) * 128 + q];
    }
#pragma unroll
    for (int i = 0; i < 4; i++) {
        int rr = r + i * 32;
        uint4 av = make_uint4(cvt_tf32(ra[i].x), cvt_tf32(ra[i].y), cvt_tf32(ra[i].z), cvt_tf32(ra[i].w));
        uint4 bv = make_uint4(cvt_tf32(rb[i].x), cvt_tf32(rb[i].y), cvt_tf32(rb[i].z), cvt_tf32(rb[i].w));
        *(uint4*)&sA[0][rr * LDS_PITCH + q * 4] = av;
        *(uint4*)&sB[0][rr * LDS_PITCH + q * 4] = bv;
    }
    __syncthreads();

    for (int ck = 0; ck < KCHUNKS; ck++) {
        const int p = ck & 1;
        // issue global loads for next chunk early
        if (ck + 1 < KCHUNKS) {
#pragma unroll
            for (int i = 0; i < 4; i++) {
                int rr = r + i * 32;
                ra[i] = A4[(size_t)(bm + rr) * 128 + (ck + 1) * 8 + q];
                rb[i] = W4[(size_t)(bn + rr) * 128 + (ck + 1) * 8 + q];
            }
        }

        const float* cA = sA[p];
        const float* cB = sB[p];
#pragma unroll
        for (int s = 0; s < 4; s++) {
            const int kc = s * 8;
            uint32_t af[4][4];
#pragma unroll
            for (int mi = 0; mi < 4; mi++) {
                const float* ap = cA + (m0w + mi * 16 + g) * LDS_PITCH + kc + t;
                af[mi][0] = __float_as_uint(ap[0]);
                af[mi][1] = __float_as_uint(ap[8 * LDS_PITCH]);
                af[mi][2] = __float_as_uint(ap[4]);
                af[mi][3] = __float_as_uint(ap[8 * LDS_PITCH + 4]);
            }
            uint32_t bf[4][2];
#pragma unroll
            for (int ni = 0; ni < 4; ni++) {
                const float* bp = cB + (n0w + ni * 8 + g) * LDS_PITCH + kc + t;
                bf[ni][0] = __float_as_uint(bp[0]);
                bf[ni][1] = __float_as_uint(bp[4]);
            }
#pragma unroll
            for (int mi = 0; mi < 4; mi++)
#pragma unroll
                for (int ni = 0; ni < 4; ni++)
                    mma_tf32(acc[mi][ni], af[mi], bf[ni]);
        }

        if (ck + 1 < KCHUNKS) {
            const int np = (ck + 1) & 1;
#pragma unroll
            for (int i = 0; i < 4; i++) {
                int rr = r + i * 32;
                uint4 av = make_uint4(cvt_tf32(ra[i].x), cvt_tf32(ra[i].y), cvt_tf32(ra[i].z), cvt_tf32(ra[i].w));
                uint4 bv = make_uint4(cvt_tf32(rb[i].x), cvt_tf32(rb[i].y), cvt_tf32(rb[i].z), cvt_tf32(rb[i].w));
                *(uint4*)&sA[np][rr * LDS_PITCH + q * 4] = av;
                *(uint4*)&sB[np][rr * LDS_PITCH + q * 4] = bv;
            }
        }
        __syncthreads();
    }

    // ---- epilogue: bias + store ----
#pragma unroll
    for (int ni = 0; ni < 4; ni++) {
        const int n = bn + n0w + ni * 8 + t * 2;
        const float b0 = __ldg(&bias[n]);
        const float b1 = __ldg(&bias[n + 1]);
#pragma unroll
        for (int mi = 0; mi < 4; mi++) {
            const int m = bm + m0w + mi * 16 + g;
            float2 v0 = make_float2(acc[mi][ni][0] + b0, acc[mi][ni][1] + b1);
            float2 v1 = make_float2(acc[mi][ni][2] + b0, acc[mi][ni][3] + b1);
            *(float2*)&C[(size_t)m * HIDDEN + n]       = v0;
            *(float2*)&C[(size_t)(m + 8) * HIDDEN + n] = v1;
        }
    }
}

// ---------------------------------------------------------------------------
// Mobius aggregation: one block per batch element, 9 warps (one per node).
// In place on the scratch buffer.
// ---------------------------------------------------------------------------
__device__ __forceinline__ float warpSum(float v) {
    v += __shfl_xor_sync(0xffffffffu, v, 16);
    v += __shfl_xor_sync(0xffffffffu, v, 8);
    v += __shfl_xor_sync(0xffffffffu, v, 4);
    v += __shfl_xor_sync(0xffffffffu, v, 2);
    v += __shfl_xor_sync(0xffffffffu, v, 1);
    return v;
}

__device__ const int d_ncnt[9]   = {3, 3, 2, 3, 3, 2, 3, 3, 8};
__device__ const int d_nbr[9][8] = {
    {4, 7, 8, 0, 0, 0, 0, 0},
    {0, 6, 8, 0, 0, 0, 0, 0},
    {5, 8, 0, 0, 0, 0, 0, 0},
    {1, 4, 8, 0, 0, 0, 0, 0},
    {6, 3, 8, 0, 0, 0, 0, 0},
    {2, 8, 0, 0, 0, 0, 0, 0},
    {7, 1, 8, 0, 0, 0, 0, 0},
    {3, 0, 8, 0, 0, 0, 0, 0},
    {0, 1, 2, 3, 4, 5, 6, 7}
};

__global__ __launch_bounds__(288)
void mobius_kernel(float* __restrict__ buf,
                   const float* __restrict__ mw,
                   const float* __restrict__ curv)
{
    __shared__ __align__(16) float sh[NUM_NODES * HIDDEN];
    __shared__ float sh_xx[NUM_NODES];

    const int b   = blockIdx.x;
    const int tid = threadIdx.x;
    const float c = fabsf(curv[0]);
    float* base = buf + (size_t)b * NUM_NODES * HIDDEN;

    for (int idx = tid; idx < NUM_NODES * HIDDEN / 4; idx += 288)
        ((float4*)sh)[idx] = ((const float4*)base)[idx];
    __syncthreads();

    const int w    = tid >> 5;
    const int lane = tid & 31;

    float r[16];
    float n2 = 0.f;
#pragma unroll
    for (int u = 0; u < 16; u++) {
        r[u] = sh[w * HIDDEN + u * 32 + lane];
        n2 += r[u] * r[u];
    }
    n2 = warpSum(n2);
    float norm  = sqrtf(n2);
    float scale = tanhf(norm) / (norm + EPS);
#pragma unroll
    for (int u = 0; u < 16; u++) {
        r[u] *= scale;
        sh[w * HIDDEN + u * 32 + lane] = r[u];
    }
    if (lane == 0) sh_xx[w] = scale * scale * n2;
    __syncthreads();

    const int cnt = d_ncnt[w];
    for (int q = 0; q < cnt; q++) {
        const int j = d_nbr[w][q];
        const float* mwp = mw + ((size_t)w * NUM_NODES + j) * HIDDEN;

        float hj[16], mv[16];
        float xy = 0.f, yy = 0.f;
#pragma unroll
        for (int u = 0; u < 16; u++) {
            hj[u] = sh[j * HIDDEN + u * 32 + lane];
            mv[u] = mwp[u * 32 + lane];
            xy += hj[u] * mv[u];
            yy += mv[u] * mv[u];
        }
        xy = warpSum(xy);
        yy = warpSum(yy);
        const float xxj = sh_xx[j];

        float ca  = 1.f + 2.f * c * xy + c * yy;
        float cb  = 1.f - c * xxj;
        float inv = 1.f / (1.f + 2.f * c * xy + c * c * xxj * yy + EPS);

        float t[16];
        float rt = 0.f, tt = 0.f, rr = 0.f;
#pragma unroll
        for (int u = 0; u < 16; u++) {
            t[u] = (ca * hj[u] + cb * mv[u]) * inv;
            rt += r[u] * t[u];
            tt += t[u] * t[u];
            rr += r[u] * r[u];
        }
        rt = warpSum(rt);
        tt = warpSum(tt);
        rr = warpSum(rr);

        float ca2  = 1.f + 2.f * c * rt + c * tt;
        float cb2  = 1.f - c * rr;
        float inv2 = 1.f / (1.f + 2.f * c * rt + c * c * rr * tt + EPS);
#pragma unroll
        for (int u = 0; u < 16; u++)
            r[u] = (ca2 * r[u] + cb2 * t[u]) * inv2;
    }

    float* dst = base + (size_t)w * HIDDEN;
#pragma unroll
    for (int u = 0; u < 16; u++)
        dst[u * 32 + lane] = r[u];
}

// ---------------------------------------------------------------------------
// kernel_launch
// ---------------------------------------------------------------------------
extern "C" void kernel_launch(void* const* d_in, const int* in_sizes, int n_in,
                              void* d_out, int out_size)
{
    const float* nf     = (const float*)d_in[0];
    const float* curv   = (const float*)d_in[1];
    const float* to_w   = (const float*)d_in[2];
    const float* to_b   = (const float*)d_in[3];
    const float* from_w = (const float*)d_in[4];
    const float* from_b = (const float*)d_in[5];
    const float* mw     = (const float*)d_in[6];
    float* out = (float*)d_out;

    float* scratch;
    cudaGetSymbolAddress((void**)&scratch, g_scratch);

    cudaFuncSetAttribute(gemm_tf32, cudaFuncAttributeMaxDynamicSharedMemorySize,
                         DYN_SMEM_BYTES);

    dim3 gg(HIDDEN / BN, M_ROWS / BM);   // (4, 576)

    // 1) x_proj = nf @ to_w.T + to_b  -> scratch   (tf32 mma.sync)
    gemm_tf32<<<gg, 256, DYN_SMEM_BYTES>>>(nf, to_w, to_b, scratch);

    // 2) tanh-normalize + mobius chains, in place
    mobius_kernel<<<BATCH, 288>>>(scratch, mw, curv);

    // 3) out = r @ from_w.T + from_b   (tf32 mma.sync)
    gemm_tf32<<<gg, 256, DYN_SMEM_BYTES>>>(scratch, from_w, from_b, out);
}

// round 4
// speedup vs baseline: 2.8179x; 1.1812x over previous
#include <cuda_runtime.h>
#include <cuda_bf16.h>
#include <math.h>
#include <cstdint>

#define NUM_NODES 9
#define HIDDEN    512
#define BATCH     8192
#define M_ROWS    (BATCH * NUM_NODES)   // 73728
#define EPS       1e-8f

// Single f32 scratch (x_proj -> h -> mobius result, in place).
__device__ float g_scratch[(size_t)M_ROWS * HIDDEN];
// Precomputed ||mw[i][j]||^2
__device__ float g_yy[NUM_NODES * NUM_NODES];

// ---------------------------------------------------------------------------
// TF32 mma.sync GEMM:  C[m][n] = sum_k A[m][k] * W[n][k] + bias[n]
// CTA tile 128x256, BK=32, 256 threads, 8 warps (2 M x 4 N), warp tile 64x64.
// Smem [row][36] padding keeps staging STS.128 and fragment LDS conflict-free.
// ---------------------------------------------------------------------------
#define BM 128
#define BN 256
#define LDS_PITCH 36                     // 32 + 4 pad (floats)
#define KCHUNKS (HIDDEN / 32)            // 16
#define A_BUF (BM * LDS_PITCH)           // 4608 floats
#define B_BUF (BN * LDS_PITCH)           // 9216 floats
#define DYN_SMEM_BYTES ((2 * A_BUF + 2 * B_BUF) * 4)   // 110592 B

__device__ __forceinline__ uint32_t cvt_tf32(float f) {
    uint32_t u;
    asm("cvt.rna.tf32.f32 %0, %1;" : "=r"(u) : "f"(f));
    return u;
}

__device__ __forceinline__ void mma_tf32(float* d, const uint32_t* a, const uint32_t* b) {
    asm volatile(
        "mma.sync.aligned.m16n8k8.row.col.f32.tf32.tf32.f32 "
        "{%0,%1,%2,%3}, {%4,%5,%6,%7}, {%8,%9}, {%0,%1,%2,%3};"
        : "+f"(d[0]), "+f"(d[1]), "+f"(d[2]), "+f"(d[3])
        : "r"(a[0]), "r"(a[1]), "r"(a[2]), "r"(a[3]), "r"(b[0]), "r"(b[1]));
}

__global__ __launch_bounds__(256)
void gemm_tf32(const float* __restrict__ A,
               const float* __restrict__ W,
               const float* __restrict__ bias,
               float* __restrict__ C)
{
    extern __shared__ __align__(16) float smem[];
    float* sA[2] = { smem,              smem + A_BUF };
    float* sB[2] = { smem + 2 * A_BUF,  smem + 2 * A_BUF + B_BUF };

    const int tid  = threadIdx.x;
    const int bm   = blockIdx.y * BM;
    const int bn   = blockIdx.x * BN;
    const int lane = tid & 31;
    const int wid  = tid >> 5;
    const int m0w  = (wid & 1) * 64;      // warp M origin
    const int n0w  = (wid >> 1) * 64;     // warp N origin
    const int g    = lane >> 2;           // 0..7
    const int t    = lane & 3;            // 0..3

    const int r = tid >> 3;               // staging row 0..31
    const int q = tid & 7;                // staging float4-col 0..7

    const float4* A4 = (const float4*)A;
    const float4* W4 = (const float4*)W;

    float acc[4][8][4];
#pragma unroll
    for (int mi = 0; mi < 4; mi++)
#pragma unroll
        for (int ni = 0; ni < 8; ni++)
#pragma unroll
            for (int e = 0; e < 4; e++) acc[mi][ni][e] = 0.f;

    float4 ra[4], rb[8];

    // ---- prologue: chunk 0 ----
#pragma unroll
    for (int i = 0; i < 4; i++)
        ra[i] = A4[(size_t)(bm + r + i * 32) * 128 + q];
#pragma unroll
    for (int i = 0; i < 8; i++)
        rb[i] = W4[(size_t)(bn + r + i * 32) * 128 + q];
#pragma unroll
    for (int i = 0; i < 4; i++) {
        uint4 v = make_uint4(cvt_tf32(ra[i].x), cvt_tf32(ra[i].y), cvt_tf32(ra[i].z), cvt_tf32(ra[i].w));
        *(uint4*)&sA[0][(r + i * 32) * LDS_PITCH + q * 4] = v;
    }
#pragma unroll
    for (int i = 0; i < 8; i++) {
        uint4 v = make_uint4(cvt_tf32(rb[i].x), cvt_tf32(rb[i].y), cvt_tf32(rb[i].z), cvt_tf32(rb[i].w));
        *(uint4*)&sB[0][(r + i * 32) * LDS_PITCH + q * 4] = v;
    }
    __syncthreads();

    for (int ck = 0; ck < KCHUNKS; ck++) {
        const int p = ck & 1;
        // issue next-chunk global loads early
        if (ck + 1 < KCHUNKS) {
#pragma unroll
            for (int i = 0; i < 4; i++)
                ra[i] = A4[(size_t)(bm + r + i * 32) * 128 + (ck + 1) * 8 + q];
#pragma unroll
            for (int i = 0; i < 8; i++)
                rb[i] = W4[(size_t)(bn + r + i * 32) * 128 + (ck + 1) * 8 + q];
        }

        const float* cA = sA[p];
        const float* cB = sB[p];
#pragma unroll
        for (int s = 0; s < 4; s++) {
            const int kc = s * 8;
            uint32_t af[4][4];
#pragma unroll
            for (int mi = 0; mi < 4; mi++) {
                const float* ap = cA + (m0w + mi * 16 + g) * LDS_PITCH + kc + t;
                af[mi][0] = __float_as_uint(ap[0]);
                af[mi][1] = __float_as_uint(ap[8 * LDS_PITCH]);
                af[mi][2] = __float_as_uint(ap[4]);
                af[mi][3] = __float_as_uint(ap[8 * LDS_PITCH + 4]);
            }
            uint32_t bf[8][2];
#pragma unroll
            for (int ni = 0; ni < 8; ni++) {
                const float* bp = cB + (n0w + ni * 8 + g) * LDS_PITCH + kc + t;
                bf[ni][0] = __float_as_uint(bp[0]);
                bf[ni][1] = __float_as_uint(bp[4]);
            }
#pragma unroll
            for (int mi = 0; mi < 4; mi++)
#pragma unroll
                for (int ni = 0; ni < 8; ni++)
                    mma_tf32(acc[mi][ni], af[mi], bf[ni]);
        }

        if (ck + 1 < KCHUNKS) {
            const int np = (ck + 1) & 1;
#pragma unroll
            for (int i = 0; i < 4; i++) {
                uint4 v = make_uint4(cvt_tf32(ra[i].x), cvt_tf32(ra[i].y), cvt_tf32(ra[i].z), cvt_tf32(ra[i].w));
                *(uint4*)&sA[np][(r + i * 32) * LDS_PITCH + q * 4] = v;
            }
#pragma unroll
            for (int i = 0; i < 8; i++) {
                uint4 v = make_uint4(cvt_tf32(rb[i].x), cvt_tf32(rb[i].y), cvt_tf32(rb[i].z), cvt_tf32(rb[i].w));
                *(uint4*)&sB[np][(r + i * 32) * LDS_PITCH + q * 4] = v;
            }
        }
        __syncthreads();
    }

    // ---- epilogue: bias + store ----
#pragma unroll
    for (int ni = 0; ni < 8; ni++) {
        const int n = bn + n0w + ni * 8 + t * 2;
        const float b0 = __ldg(&bias[n]);
        const float b1 = __ldg(&bias[n + 1]);
#pragma unroll
        for (int mi = 0; mi < 4; mi++) {
            const int m = bm + m0w + mi * 16 + g;
            float2 v0 = make_float2(acc[mi][ni][0] + b0, acc[mi][ni][1] + b1);
            float2 v1 = make_float2(acc[mi][ni][2] + b0, acc[mi][ni][3] + b1);
            *(float2*)&C[(size_t)m * HIDDEN + n]       = v0;
            *(float2*)&C[(size_t)(m + 8) * HIDDEN + n] = v1;
        }
    }
}

// ---------------------------------------------------------------------------
// warp reduction
// ---------------------------------------------------------------------------
__device__ __forceinline__ float warpSum(float v) {
    v += __shfl_xor_sync(0xffffffffu, v, 16);
    v += __shfl_xor_sync(0xffffffffu, v, 8);
    v += __shfl_xor_sync(0xffffffffu, v, 4);
    v += __shfl_xor_sync(0xffffffffu, v, 2);
    v += __shfl_xor_sync(0xffffffffu, v, 1);
    return v;
}

// Precompute ||mw[i][j]||^2 for all 81 pairs.
__global__ void yy_kernel(const float* __restrict__ mw) {
    const int idx  = blockIdx.x;        // 0..80
    const int lane = threadIdx.x;
    const float* p = mw + (size_t)idx * HIDDEN;
    float s = 0.f;
#pragma unroll
    for (int u = 0; u < 16; u++) { float v = p[u * 32 + lane]; s += v * v; }
    s = warpSum(s);
    if (lane == 0) g_yy[idx] = s;
}

// ---------------------------------------------------------------------------
// Mobius aggregation: one block per batch element, 9 warps (one per node).
// Only 2 warp reductions per neighbor op (xy, rt); yy precomputed,
// tt/rr maintained algebraically.
// ---------------------------------------------------------------------------
__device__ const int d_ncnt[9]   = {3, 3, 2, 3, 3, 2, 3, 3, 8};
__device__ const int d_nbr[9][8] = {
    {4, 7, 8, 0, 0, 0, 0, 0},
    {0, 6, 8, 0, 0, 0, 0, 0},
    {5, 8, 0, 0, 0, 0, 0, 0},
    {1, 4, 8, 0, 0, 0, 0, 0},
    {6, 3, 8, 0, 0, 0, 0, 0},
    {2, 8, 0, 0, 0, 0, 0, 0},
    {7, 1, 8, 0, 0, 0, 0, 0},
    {3, 0, 8, 0, 0, 0, 0, 0},
    {0, 1, 2, 3, 4, 5, 6, 7}
};

__global__ __launch_bounds__(288)
void mobius_kernel(float* __restrict__ buf,
                   const float* __restrict__ mw,
                   const float* __restrict__ curv)
{
    __shared__ __align__(16) float sh[NUM_NODES * HIDDEN];
    __shared__ float sh_xx[NUM_NODES];

    const int b   = blockIdx.x;
    const int tid = threadIdx.x;
    const float c = fabsf(curv[0]);
    float* base = buf + (size_t)b * NUM_NODES * HIDDEN;

    for (int idx = tid; idx < NUM_NODES * HIDDEN / 4; idx += 288)
        ((float4*)sh)[idx] = ((const float4*)base)[idx];
    __syncthreads();

    const int w    = tid >> 5;
    const int lane = tid & 31;

    // tanh-normalize node w
    float r[16];
    float n2 = 0.f;
#pragma unroll
    for (int u = 0; u < 16; u++) {
        r[u] = sh[w * HIDDEN + u * 32 + lane];
        n2 += r[u] * r[u];
    }
    n2 = warpSum(n2);
    float norm  = sqrtf(n2);
    float scale = tanhf(norm) / (norm + EPS);
    float rr = scale * scale * n2;        // ||h_w||^2, maintained by recurrence
#pragma unroll
    for (int u = 0; u < 16; u++) {
        r[u] *= scale;
        sh[w * HIDDEN + u * 32 + lane] = r[u];
    }
    if (lane == 0) sh_xx[w] = rr;
    __syncthreads();

    const int cnt = d_ncnt[w];
    for (int q = 0; q < cnt; q++) {
        const int j = d_nbr[w][q];
        const float* mwp = mw + ((size_t)w * NUM_NODES + j) * HIDDEN;
        const float yy = __ldg(&g_yy[w * NUM_NODES + j]);

        float hj[16], mv[16];
        float xy = 0.f;
#pragma unroll
        for (int u = 0; u < 16; u++) {
            hj[u] = sh[j * HIDDEN + u * 32 + lane];
            mv[u] = __ldg(&mwp[u * 32 + lane]);
            xy += hj[u] * mv[u];
        }
        xy = warpSum(xy);
        const float xxj = sh_xx[j];

        // t = mobius_add(h_j, mw_ij, c)
        const float ca  = 1.f + 2.f * c * xy + c * yy;
        const float cb  = 1.f - c * xxj;
        const float inv = 1.f / (1.f + 2.f * c * xy + c * c * xxj * yy + EPS);
        const float tt  = inv * inv * (ca * ca * xxj + 2.f * ca * cb * xy + cb * cb * yy);

        float t[16];
        float rt = 0.f;
#pragma unroll
        for (int u = 0; u < 16; u++) {
            t[u] = (ca * hj[u] + cb * mv[u]) * inv;
            rt += r[u] * t[u];
        }
        rt = warpSum(rt);

        // r = mobius_add(r, t, c)
        const float ca2  = 1.f + 2.f * c * rt + c * tt;
        const float cb2  = 1.f - c * rr;
        const float inv2 = 1.f / (1.f + 2.f * c * rt + c * c * rr * tt + EPS);
#pragma unroll
        for (int u = 0; u < 16; u++)
            r[u] = (ca2 * r[u] + cb2 * t[u]) * inv2;
        rr = inv2 * inv2 * (ca2 * ca2 * rr + 2.f * ca2 * cb2 * rt + cb2 * cb2 * tt);
    }

    float* dst = base + (size_t)w * HIDDEN;
#pragma unroll
    for (int u = 0; u < 16; u++)
        dst[u * 32 + lane] = r[u];
}

// ---------------------------------------------------------------------------
// kernel_launch
// ---------------------------------------------------------------------------
extern "C" void kernel_launch(void* const* d_in, const int* in_sizes, int n_in,
                              void* d_out, int out_size)
{
    const float* nf     = (const float*)d_in[0];
    const float* curv   = (const float*)d_in[1];
    const float* to_w   = (const float*)d_in[2];
    const float* to_b   = (const float*)d_in[3];
    const float* from_w = (const float*)d_in[4];
    const float* from_b = (const float*)d_in[5];
    const float* mw     = (const float*)d_in[6];
    float* out = (float*)d_out;

    float* scratch;
    cudaGetSymbolAddress((void**)&scratch, g_scratch);

    cudaFuncSetAttribute(gemm_tf32, cudaFuncAttributeMaxDynamicSharedMemorySize,
                         DYN_SMEM_BYTES);

    dim3 gg(HIDDEN / BN, M_ROWS / BM);   // (2, 576)

    // 0) ||mw||^2 per (i,j)
    yy_kernel<<<NUM_NODES * NUM_NODES, 32>>>(mw);

    // 1) x_proj = nf @ to_w.T + to_b  -> scratch   (tf32 mma.sync)
    gemm_tf32<<<gg, 256, DYN_SMEM_BYTES>>>(nf, to_w, to_b, scratch);

    // 2) tanh-normalize + mobius chains, in place
    mobius_kernel<<<BATCH, 288>>>(scratch, mw, curv);

    // 3) out = r @ from_w.T + from_b   (tf32 mma.sync)
    gemm_tf32<<<gg, 256, DYN_SMEM_BYTES>>>(scratch, from_w, from_b, out);
}

// round 5
// speedup vs baseline: 3.3421x; 1.1860x over previous
#include <cuda_runtime.h>
#include <cuda_bf16.h>
#include <math.h>
#include <cstdint>

#define NUM_NODES 9
#define HIDDEN    512
#define BATCH     8192
#define M_ROWS    (BATCH * NUM_NODES)   // 73728
#define EPS       1e-8f

// Scratch buffers (device globals; no dynamic alloc allowed).
__device__ float g_scratch[(size_t)M_ROWS * HIDDEN];   // x_proj -> h -> mobius out (tf32-rounded)
__device__ float g_a[(size_t)M_ROWS * HIDDEN];         // tf32-rounded nf
__device__ float g_w1[HIDDEN * HIDDEN];                // tf32-rounded to_w
__device__ float g_w2[HIDDEN * HIDDEN];                // tf32-rounded from_w
__device__ float g_yy[NUM_NODES * NUM_NODES];          // ||mw[i][j]||^2

__device__ __forceinline__ uint32_t smem_u32(const void* p) {
    uint32_t a;
    asm("{ .reg .u64 t; cvta.to.shared.u64 t, %1; cvt.u32.u64 %0, t; }" : "=r"(a) : "l"(p));
    return a;
}
__device__ __forceinline__ uint32_t cvt_tf32(float f) {
    uint32_t u;
    asm("cvt.rna.tf32.f32 %0, %1;" : "=r"(u) : "f"(f));
    return u;
}

#define CP_ASYNC16(saddr, gptr) \
    asm volatile("cp.async.cg.shared.global [%0], [%1], 16;" :: "r"(saddr), "l"(gptr) : "memory")
#define CP_COMMIT() asm volatile("cp.async.commit_group;" ::: "memory")
#define CP_WAIT(n)  asm volatile("cp.async.wait_group %0;" :: "n"(n) : "memory")

__device__ __forceinline__ void mma_tf32(float* d, const uint32_t* a, const uint32_t* b) {
    asm volatile(
        "mma.sync.aligned.m16n8k8.row.col.f32.tf32.tf32.f32 "
        "{%0,%1,%2,%3}, {%4,%5,%6,%7}, {%8,%9}, {%0,%1,%2,%3};"
        : "+f"(d[0]), "+f"(d[1]), "+f"(d[2]), "+f"(d[3])
        : "r"(a[0]), "r"(a[1]), "r"(a[2]), "r"(a[3]), "r"(b[0]), "r"(b[1]));
}

// ---------------------------------------------------------------------------
// tf32 round prepass (bandwidth-bound)
// ---------------------------------------------------------------------------
__global__ void round_kernel(const float4* __restrict__ in, float4* __restrict__ out, int n4) {
    int i = blockIdx.x * blockDim.x + threadIdx.x;
    int stride = gridDim.x * blockDim.x;
    for (; i < n4; i += stride) {
        float4 v = in[i];
        uint4 u = make_uint4(cvt_tf32(v.x), cvt_tf32(v.y), cvt_tf32(v.z), cvt_tf32(v.w));
        out[i] = *(float4*)&u;
    }
}

// ---------------------------------------------------------------------------
// TF32 mma.sync GEMM with cp.async 3-stage pipeline.
// C[m][n] = sum_k A[m][k]*W[n][k] + bias[n].  A, W pre-rounded to tf32.
// CTA 128x256, BK=32, 256 threads, 8 warps (2M x 4N), warp tile 64x64.
// Smem pitch 36 floats (conflict-free fragment LDS, 16B-aligned cp.async).
// ---------------------------------------------------------------------------
#define BM 128
#define BN 256
#define LDS_PITCH 36
#define KCHUNKS (HIDDEN / 32)            // 16
#define A_BUF (BM * LDS_PITCH)           // 4608 floats / stage
#define B_BUF (BN * LDS_PITCH)           // 9216 floats / stage
#define STAGES 3
#define DYN_SMEM_BYTES (STAGES * (A_BUF + B_BUF) * 4)   // 165888 B

__global__ __launch_bounds__(256)
void gemm_cp(const float* __restrict__ A,
             const float* __restrict__ W,
             const float* __restrict__ bias,
             float* __restrict__ C)
{
    extern __shared__ __align__(16) float smem[];
    const uint32_t smem_base = smem_u32(smem);
    const uint32_t sA0 = smem_base;
    const uint32_t sB0 = smem_base + STAGES * A_BUF * 4;

    const int tid  = threadIdx.x;
    const int bm   = blockIdx.y * BM;
    const int bn   = blockIdx.x * BN;
    const int lane = tid & 31;
    const int wid  = tid >> 5;
    const int m0w  = (wid & 1) * 64;
    const int n0w  = (wid >> 1) * 64;
    const int g    = lane >> 2;
    const int t    = lane & 3;

    const int r = tid >> 3;               // 0..31
    const int q = tid & 7;                // 0..7

    // per-thread staging bases
    const float* aG = A + (size_t)(bm + r) * HIDDEN + q * 4;
    const float* bG = W + (size_t)(bn + r) * HIDDEN + q * 4;
    const uint32_t aS = sA0 + (uint32_t)(r * LDS_PITCH + q * 4) * 4;
    const uint32_t bS = sB0 + (uint32_t)(r * LDS_PITCH + q * 4) * 4;

    float acc[4][8][4];
#pragma unroll
    for (int mi = 0; mi < 4; mi++)
#pragma unroll
        for (int ni = 0; ni < 8; ni++)
#pragma unroll
            for (int e = 0; e < 4; e++) acc[mi][ni][e] = 0.f;

#define ISSUE_STAGE(ck, st) do { \
    const float* _ag = aG + (ck) * 32; \
    const float* _bg = bG + (ck) * 32; \
    uint32_t _as = aS + (uint32_t)(st) * (A_BUF * 4); \
    uint32_t _bs = bS + (uint32_t)(st) * (B_BUF * 4); \
    _Pragma("unroll") \
    for (int _i = 0; _i < 4; _i++) \
        CP_ASYNC16(_as + _i * 32 * LDS_PITCH * 4, _ag + (size_t)_i * 32 * HIDDEN); \
    _Pragma("unroll") \
    for (int _i = 0; _i < 8; _i++) \
        CP_ASYNC16(_bs + _i * 32 * LDS_PITCH * 4, _bg + (size_t)_i * 32 * HIDDEN); \
    CP_COMMIT(); \
} while (0)

    ISSUE_STAGE(0, 0);
    ISSUE_STAGE(1, 1);

    uint32_t af[2][4][4], bf[2][8][2];

    int st = 0;
    for (int ck = 0; ck < KCHUNKS; ck++) {
        if (ck < KCHUNKS - 1) { CP_WAIT(1); } else { CP_WAIT(0); }
        __syncthreads();
        if (ck + 2 < KCHUNKS) {
            int nst = st + 2; if (nst >= STAGES) nst -= STAGES;
            ISSUE_STAGE(ck + 2, nst);
        }

        const float* cA = smem + st * A_BUF;
        const float* cB = smem + STAGES * A_BUF + st * B_BUF;

        // load step-0 fragments
#pragma unroll
        for (int mi = 0; mi < 4; mi++) {
            const float* ap = cA + (m0w + mi * 16 + g) * LDS_PITCH + t;
            af[0][mi][0] = __float_as_uint(ap[0]);
            af[0][mi][1] = __float_as_uint(ap[8 * LDS_PITCH]);
            af[0][mi][2] = __float_as_uint(ap[4]);
            af[0][mi][3] = __float_as_uint(ap[8 * LDS_PITCH + 4]);
        }
#pragma unroll
        for (int ni = 0; ni < 8; ni++) {
            const float* bp = cB + (n0w + ni * 8 + g) * LDS_PITCH + t;
            bf[0][ni][0] = __float_as_uint(bp[0]);
            bf[0][ni][1] = __float_as_uint(bp[4]);
        }

#pragma unroll
        for (int s = 0; s < 4; s++) {
            const int cur = s & 1;
            if (s < 3) {
                const int nxt = cur ^ 1;
                const int kc = (s + 1) * 8;
#pragma unroll
                for (int mi = 0; mi < 4; mi++) {
                    const float* ap = cA + (m0w + mi * 16 + g) * LDS_PITCH + kc + t;
                    af[nxt][mi][0] = __float_as_uint(ap[0]);
                    af[nxt][mi][1] = __float_as_uint(ap[8 * LDS_PITCH]);
                    af[nxt][mi][2] = __float_as_uint(ap[4]);
                    af[nxt][mi][3] = __float_as_uint(ap[8 * LDS_PITCH + 4]);
                }
#pragma unroll
                for (int ni = 0; ni < 8; ni++) {
                    const float* bp = cB + (n0w + ni * 8 + g) * LDS_PITCH + kc + t;
                    bf[nxt][ni][0] = __float_as_uint(bp[0]);
                    bf[nxt][ni][1] = __float_as_uint(bp[4]);
                }
            }
#pragma unroll
            for (int mi = 0; mi < 4; mi++)
#pragma unroll
                for (int ni = 0; ni < 8; ni++)
                    mma_tf32(acc[mi][ni], af[cur][mi], bf[cur][ni]);
        }

        st++; if (st >= STAGES) st -= STAGES;
    }

    // epilogue: bias + store
#pragma unroll
    for (int ni = 0; ni < 8; ni++) {
        const int n = bn + n0w + ni * 8 + t * 2;
        const float b0 = __ldg(&bias[n]);
        const float b1 = __ldg(&bias[n + 1]);
#pragma unroll
        for (int mi = 0; mi < 4; mi++) {
            const int m = bm + m0w + mi * 16 + g;
            float2 v0 = make_float2(acc[mi][ni][0] + b0, acc[mi][ni][1] + b1);
            float2 v1 = make_float2(acc[mi][ni][2] + b0, acc[mi][ni][3] + b1);
            *(float2*)&C[(size_t)m * HIDDEN + n]       = v0;
            *(float2*)&C[(size_t)(m + 8) * HIDDEN + n] = v1;
        }
    }
}

// ---------------------------------------------------------------------------
// warp reduction + yy precompute
// ---------------------------------------------------------------------------
__device__ __forceinline__ float warpSum(float v) {
    v += __shfl_xor_sync(0xffffffffu, v, 16);
    v += __shfl_xor_sync(0xffffffffu, v, 8);
    v += __shfl_xor_sync(0xffffffffu, v, 4);
    v += __shfl_xor_sync(0xffffffffu, v, 2);
    v += __shfl_xor_sync(0xffffffffu, v, 1);
    return v;
}

__global__ void yy_kernel(const float* __restrict__ mw) {
    const int idx  = blockIdx.x;
    const int lane = threadIdx.x;
    const float* p = mw + (size_t)idx * HIDDEN;
    float s = 0.f;
#pragma unroll
    for (int u = 0; u < 16; u++) { float v = p[u * 32 + lane]; s += v * v; }
    s = warpSum(s);
    if (lane == 0) g_yy[idx] = s;
}

// ---------------------------------------------------------------------------
// Mobius aggregation: one block per batch element, 9 warps (one per node).
// Writes tf32-rounded output (consumed only by GEMM2).
// ---------------------------------------------------------------------------
__device__ const int d_ncnt[9]   = {3, 3, 2, 3, 3, 2, 3, 3, 8};
__device__ const int d_nbr[9][8] = {
    {4, 7, 8, 0, 0, 0, 0, 0},
    {0, 6, 8, 0, 0, 0, 0, 0},
    {5, 8, 0, 0, 0, 0, 0, 0},
    {1, 4, 8, 0, 0, 0, 0, 0},
    {6, 3, 8, 0, 0, 0, 0, 0},
    {2, 8, 0, 0, 0, 0, 0, 0},
    {7, 1, 8, 0, 0, 0, 0, 0},
    {3, 0, 8, 0, 0, 0, 0, 0},
    {0, 1, 2, 3, 4, 5, 6, 7}
};

__global__ __launch_bounds__(288)
void mobius_kernel(float* __restrict__ buf,
                   const float* __restrict__ mw,
                   const float* __restrict__ curv)
{
    __shared__ __align__(16) float sh[NUM_NODES * HIDDEN];
    __shared__ float sh_xx[NUM_NODES];

    const int b   = blockIdx.x;
    const int tid = threadIdx.x;
    const float c = fabsf(curv[0]);
    float* base = buf + (size_t)b * NUM_NODES * HIDDEN;

    for (int idx = tid; idx < NUM_NODES * HIDDEN / 4; idx += 288)
        ((float4*)sh)[idx] = ((const float4*)base)[idx];
    __syncthreads();

    const int w    = tid >> 5;
    const int lane = tid & 31;

    float r[16];
    float n2 = 0.f;
#pragma unroll
    for (int u = 0; u < 16; u++) {
        r[u] = sh[w * HIDDEN + u * 32 + lane];
        n2 += r[u] * r[u];
    }
    n2 = warpSum(n2);
    float norm  = sqrtf(n2);
    float scale = tanhf(norm) / (norm + EPS);
    float rr = scale * scale * n2;
#pragma unroll
    for (int u = 0; u < 16; u++) {
        r[u] *= scale;
        sh[w * HIDDEN + u * 32 + lane] = r[u];
    }
    if (lane == 0) sh_xx[w] = rr;
    __syncthreads();

    const int cnt = d_ncnt[w];
    for (int q = 0; q < cnt; q++) {
        const int j = d_nbr[w][q];
        const float* mwp = mw + ((size_t)w * NUM_NODES + j) * HIDDEN;
        const float yy = __ldg(&g_yy[w * NUM_NODES + j]);

        float hj[16], mv[16];
        float xy = 0.f;
#pragma unroll
        for (int u = 0; u < 16; u++) {
            hj[u] = sh[j * HIDDEN + u * 32 + lane];
            mv[u] = __ldg(&mwp[u * 32 + lane]);
            xy += hj[u] * mv[u];
        }
        xy = warpSum(xy);
        const float xxj = sh_xx[j];

        const float ca  = 1.f + 2.f * c * xy + c * yy;
        const float cb  = 1.f - c * xxj;
        const float inv = 1.f / (1.f + 2.f * c * xy + c * c * xxj * yy + EPS);
        const float tt  = inv * inv * (ca * ca * xxj + 2.f * ca * cb * xy + cb * cb * yy);

        float t[16];
        float rt = 0.f;
#pragma unroll
        for (int u = 0; u < 16; u++) {
            t[u] = (ca * hj[u] + cb * mv[u]) * inv;
            rt += r[u] * t[u];
        }
        rt = warpSum(rt);

        const float ca2  = 1.f + 2.f * c * rt + c * tt;
        const float cb2  = 1.f - c * rr;
        const float inv2 = 1.f / (1.f + 2.f * c * rt + c * c * rr * tt + EPS);
#pragma unroll
        for (int u = 0; u < 16; u++)
            r[u] = (ca2 * r[u] + cb2 * t[u]) * inv2;
        rr = inv2 * inv2 * (ca2 * ca2 * rr + 2.f * ca2 * cb2 * rt + cb2 * cb2 * tt);
    }

    // store tf32-rounded (GEMM2 consumes without further conversion)
    float* dst = base + (size_t)w * HIDDEN;
#pragma unroll
    for (int u = 0; u < 16; u++)
        dst[u * 32 + lane] = __uint_as_float(cvt_tf32(r[u]));
}

// ---------------------------------------------------------------------------
// kernel_launch
// ---------------------------------------------------------------------------
extern "C" void kernel_launch(void* const* d_in, const int* in_sizes, int n_in,
                              void* d_out, int out_size)
{
    const float* nf     = (const float*)d_in[0];
    const float* curv   = (const float*)d_in[1];
    const float* to_w   = (const float*)d_in[2];
    const float* to_b   = (const float*)d_in[3];
    const float* from_w = (const float*)d_in[4];
    const float* from_b = (const float*)d_in[5];
    const float* mw     = (const float*)d_in[6];
    float* out = (float*)d_out;

    float *scratch, *a_rnd, *w1, *w2;
    cudaGetSymbolAddress((void**)&scratch, g_scratch);
    cudaGetSymbolAddress((void**)&a_rnd,   g_a);
    cudaGetSymbolAddress((void**)&w1,      g_w1);
    cudaGetSymbolAddress((void**)&w2,      g_w2);

    cudaFuncSetAttribute(gemm_cp, cudaFuncAttributeMaxDynamicSharedMemorySize,
                         DYN_SMEM_BYTES);

    dim3 gg(HIDDEN / BN, M_ROWS / BM);   // (2, 576)

    // prepasses (bandwidth-bound / tiny)
    round_kernel<<<4096, 256>>>((const float4*)nf, (float4*)a_rnd, M_ROWS * HIDDEN / 4);
    round_kernel<<<128, 256>>>((const float4*)to_w,   (float4*)w1, HIDDEN * HIDDEN / 4);
    round_kernel<<<128, 256>>>((const float4*)from_w, (float4*)w2, HIDDEN * HIDDEN / 4);
    yy_kernel<<<NUM_NODES * NUM_NODES, 32>>>(mw);

    // 1) x_proj = nf @ to_w.T + to_b  -> scratch
    gemm_cp<<<gg, 256, DYN_SMEM_BYTES>>>(a_rnd, w1, to_b, scratch);

    // 2) tanh-normalize + mobius chains, in place (writes tf32-rounded)
    mobius_kernel<<<BATCH, 288>>>(scratch, mw, curv);

    // 3) out = r @ from_w.T + from_b
    gemm_cp<<<gg, 256, DYN_SMEM_BYTES>>>(scratch, w2, from_b, out);
}